// round 7
// baseline (speedup 1.0000x reference)
#include <cuda_runtime.h>
#include <stdint.h>
#include <math_constants.h>

#define K_CODES 8192
#define DIM     256
#define NTOK    32768
#define HW      1024

// output layout (floats): loss | quantized | indices | new_count | new_weight | new_codebook
#define OUT_LOSS 0
#define OUT_Q    1
#define OUT_IDX  (OUT_Q  + 32*DIM*HW)
#define OUT_CNT  (OUT_IDX + NTOK)
#define OUT_W    (OUT_CNT + K_CODES)
#define OUT_CB   (OUT_W   + K_CODES*DIM)

// ---------------- device scratch ----------------
__device__ __align__(128) float g_xhi[NTOK * DIM];      // x layout: [b][d][hw]
__device__ __align__(128) float g_xlo[NTOK * DIM];
__device__ __align__(128) float g_cbhiT[DIM * K_CODES]; // transposed: [d][code]
__device__ __align__(128) float g_cbloT[DIM * K_CODES];
__device__ float              g_cbnorm[K_CODES];
__device__ float              g_znorm[NTOK];
__device__ unsigned long long g_best[NTOK];
__device__ float              g_counts[K_CODES];
__device__ float              g_dw[K_CODES * DIM];
__device__ double             g_loss;
__device__ int                g_idx[NTOK];

__device__ __forceinline__ uint32_t smem_u32(const void* p) {
    uint32_t a;
    asm("{ .reg .u64 t; cvta.to.shared.u64 t, %1; cvt.u32.u64 %0, t; }" : "=r"(a) : "l"(p));
    return a;
}
__device__ __forceinline__ float to_tf32(float v) {
    uint32_t u;
    asm("cvt.rna.satfinite.tf32.f32 %0, %1;" : "=r"(u) : "f"(v));
    return __uint_as_float(u);
}
#define CP16(dst, src) \
    asm volatile("cp.async.ca.shared.global [%0], [%1], 16;" :: "r"(dst), "l"(src))
#define CP_COMMIT() asm volatile("cp.async.commit_group;" ::: "memory")
#define CP_WAIT1()  asm volatile("cp.async.wait_group 1;" ::: "memory")
#define CP_WAIT0()  asm volatile("cp.async.wait_group 0;" ::: "memory")

#define MMA_TF32(c, a, b) \
    asm volatile("mma.sync.aligned.m16n8k8.row.col.f32.tf32.tf32.f32 " \
        "{%0,%1,%2,%3}, {%4,%5,%6,%7}, {%8,%9}, {%0,%1,%2,%3};" \
        : "+f"((c)[0]), "+f"((c)[1]), "+f"((c)[2]), "+f"((c)[3]) \
        : "r"((a)[0]), "r"((a)[1]), "r"((a)[2]), "r"((a)[3]), "r"((b)[0]), "r"((b)[1]))

// ---------------- init ----------------
__global__ void init_kernel() {
    int i = blockIdx.x * blockDim.x + threadIdx.x;
    if (i < K_CODES * DIM) g_dw[i] = 0.0f;
    if (i < NTOK)          g_best[i] = 0xFFFFFFFFFFFFFFFFull;
    if (i < K_CODES)       g_counts[i] = 0.0f;
    if (i == 0)            g_loss = 0.0;
}

// ---------------- decompose x -> tf32 hi/lo (same layout) ----------------
__global__ void decomp_x(const float* __restrict__ x) {
    int i = blockIdx.x * blockDim.x + threadIdx.x;
    float v  = x[i];
    float hi = to_tf32(v);
    g_xhi[i] = hi;
    g_xlo[i] = to_tf32(v - hi);
}

// ---------------- decompose + transpose codebook -> [d][code] hi/lo ----------------
__global__ void decomp_cbT(const float* __restrict__ cb) {
    __shared__ float tile[32][33];
    int tx = threadIdx.x, ty = threadIdx.y;
    int c0 = blockIdx.x * 32, d0 = blockIdx.y * 32;
    tile[ty][tx] = cb[(size_t)(c0 + ty) * DIM + d0 + tx];
    __syncthreads();
    float v  = tile[tx][ty];                  // code = c0+tx, d = d0+ty
    float hi = to_tf32(v);
    size_t o = (size_t)(d0 + ty) * K_CODES + c0 + tx;
    g_cbhiT[o] = hi;
    g_cbloT[o] = to_tf32(v - hi);
}

// ---------------- token norms (fp64 -> fp32), 4-way ILP ----------------
__global__ void znorm_kernel(const float* __restrict__ x) {
    int token = blockIdx.x * blockDim.x + threadIdx.x;
    int b = token >> 10, hw = token & 1023;
    const float* p = x + (size_t)b * DIM * HW + hw;
    double s0 = 0.0, s1 = 0.0, s2 = 0.0, s3 = 0.0;
    #pragma unroll 4
    for (int d = 0; d < DIM; d += 4) {
        double v0 = (double)p[(size_t)(d + 0) * HW];
        double v1 = (double)p[(size_t)(d + 1) * HW];
        double v2 = (double)p[(size_t)(d + 2) * HW];
        double v3 = (double)p[(size_t)(d + 3) * HW];
        s0 = fma(v0, v0, s0);
        s1 = fma(v1, v1, s1);
        s2 = fma(v2, v2, s2);
        s3 = fma(v3, v3, s3);
    }
    g_znorm[token] = (float)((s0 + s1) + (s2 + s3));
}

// ---------------- codebook norms (fp64 -> fp32) ----------------
__global__ void cbnorm_kernel(const float* __restrict__ cb) {
    int gt = blockIdx.x * blockDim.x + threadIdx.x;
    int code = gt >> 5, lane = gt & 31;
    if (code >= K_CODES) return;
    const float* r = cb + (size_t)code * DIM;
    double s = 0.0;
    #pragma unroll
    for (int i = lane; i < DIM; i += 32) {
        double v = (double)__ldg(r + i);
        s = fma(v, v, s);
    }
    #pragma unroll
    for (int o = 16; o; o >>= 1) s += __shfl_down_sync(0xFFFFFFFFu, s, o);
    if (lane == 0) g_cbnorm[code] = (float)s;
}

// ---------------- 3xTF32 mma.sync distance GEMM + argmin (concat-K) ----------------
// grid (64, 256): 128 codes x 128 tokens per CTA.
// K' = 768 as 24 chunks of 32: term 0 (Ahi,Bhi), term 1 (Ahi,Blo), term 2 (Alo,Bhi).
// Per stage: A 32x136f + B 32x136f = 34816B; 2 stages = 69632B -> 2 CTAs/SM.
#define ROWP    136
#define ARR_F   (32 * ROWP)          // 4352 floats per array
#define STAGE_F (2 * ARR_F)          // 8704 floats per stage
#define SMEM_B  (2 * STAGE_F * 4)    // 69632 bytes
#define NCHUNK  24

__global__ void __launch_bounds__(256, 2)
gemm_argmin_tc(void) {
    extern __shared__ float smf[];
    const uint32_t smb = smem_u32(smf);

    const int tid  = threadIdx.x;
    const int lane = tid & 31;
    const int wid  = tid >> 5;
    const int g    = lane >> 2;        // 0..7
    const int q    = lane & 3;         // 0..3

    const int tb  = blockIdx.y;                   // token tile
    const int ct  = blockIdx.x;                   // code tile
    const int b   = (tb * 128) >> 10;
    const int hw0 = (tb * 128) & 1023;
    const int nt0 = ct * 128;

    const int mbase = (wid & 3) * 32;   // warp token offset
    const int nbase = (wid >> 2) * 64;  // warp code offset

    float acc[2][8][4];
    #pragma unroll
    for (int mf = 0; mf < 2; mf++)
        #pragma unroll
        for (int nf = 0; nf < 8; nf++)
            #pragma unroll
            for (int c = 0; c < 4; c++) acc[mf][nf][c] = 0.0f;

    // stage issue: chunk -> (term, k0); A tile 32x128f, B tile 32x128f.
    auto issue = [&](int s, int chunk) {
        const int term = chunk >> 3;
        const int k0   = (chunk & 7) * 32;
        const float* ap = ((term == 2) ? g_xlo : g_xhi)
                        + ((size_t)(b * DIM + k0) << 10) + hw0;
        const float* bp = ((term == 1) ? g_cbloT : g_cbhiT)
                        + ((size_t)k0 << 13) + nt0;
        #pragma unroll
        for (int i = 0; i < 4; i++) {
            int idx = i * 256 + tid;         // 0..1023
            int row = idx >> 5;              // 0..31
            int seg = (idx & 31) * 4;        // 0..124
            uint32_t da = smb + 4u * (s * STAGE_F + row * ROWP + seg);
            uint32_t db = smb + 4u * (s * STAGE_F + ARR_F + row * ROWP + seg);
            CP16(da, ap + (size_t)row * 1024 + seg);
            CP16(db, bp + (size_t)row * 8192 + seg);
        }
        CP_COMMIT();
    };

    issue(0, 0);

    #pragma unroll 1
    for (int ks = 0; ks < NCHUNK; ks++) {
        if (ks < NCHUNK - 1) issue((ks + 1) & 1, ks + 1);
        if (ks < NCHUNK - 1) CP_WAIT1(); else CP_WAIT0();
        __syncthreads();

        const uint32_t* Ah = (const uint32_t*)(smf + (ks & 1) * STAGE_F);
        const uint32_t* Bh = Ah + ARR_F;

        #pragma unroll
        for (int kk = 0; kk < 4; kk++) {
            const int r0 = kk * 8 + q;
            const int r1 = r0 + 4;
            uint32_t af[2][4], bf[8][2];
            #pragma unroll
            for (int mf = 0; mf < 2; mf++) {
                int m = mbase + mf * 16 + g;
                af[mf][0] = Ah[r0 * ROWP + m];
                af[mf][1] = Ah[r0 * ROWP + m + 8];
                af[mf][2] = Ah[r1 * ROWP + m];
                af[mf][3] = Ah[r1 * ROWP + m + 8];
            }
            #pragma unroll
            for (int nf = 0; nf < 8; nf++) {
                int n = nbase + nf * 8 + g;
                bf[nf][0] = Bh[r0 * ROWP + n];
                bf[nf][1] = Bh[r1 * ROWP + n];
            }
            #pragma unroll
            for (int mf = 0; mf < 2; mf++)
                #pragma unroll
                for (int nf = 0; nf < 8; nf++)
                    MMA_TF32(acc[mf][nf], af[mf], bf[nf]);
        }
        __syncthreads();
    }

    // epilogue: d = fl( fl(zn+cn) - 2*dot ), lexicographic (d, idx) min.
    // C frag: c0/c1 at row g (cols 2q, 2q+1), c2/c3 at row g+8.
    #pragma unroll
    for (int mf = 0; mf < 2; mf++) {
        #pragma unroll
        for (int h = 0; h < 2; h++) {
            int m = mbase + mf * 16 + g + h * 8;
            int token = tb * 128 + m;
            float zn = g_znorm[token];
            unsigned long long bestpk = 0xFFFFFFFFFFFFFFFFull;
            #pragma unroll
            for (int nf = 0; nf < 8; nf++) {
                #pragma unroll
                for (int p = 0; p < 2; p++) {
                    int n = nbase + nf * 8 + q * 2 + p;
                    float dot = acc[mf][nf][h * 2 + p];
                    float cn  = __ldg(&g_cbnorm[nt0 + n]);
                    float t1  = __fadd_rn(zn, cn);
                    float d   = __fsub_rn(t1, __fmul_rn(2.0f, dot));
                    unsigned int e = __float_as_uint(d);
                    e = (e & 0x80000000u) ? ~e : (e | 0x80000000u);
                    unsigned long long pk =
                        ((unsigned long long)e << 32) | (unsigned int)(nt0 + n);
                    if (pk < bestpk) bestpk = pk;
                }
            }
            atomicMin(&g_best[token], bestpk);
        }
    }
}

// ---------------- extract indices, bump counts ----------------
__global__ void post_idx(float* __restrict__ out) {
    int n = blockIdx.x * blockDim.x + threadIdx.x;
    if (n >= NTOK) return;
    unsigned long long pk = g_best[n];
    int id = (int)(pk & 0xFFFFFFFFull);
    g_idx[n] = id;
    out[OUT_IDX + n] = (float)id;
    atomicAdd(&g_counts[id], 1.0f);
}

// ---------------- quantized output + commitment loss (coalesced) ----------------
// grid (DIM, 32): block = (c, b); 256 threads x 4 iters over hw.
__global__ void quant_loss(const float* __restrict__ x,
                           const float* __restrict__ cb,
                           float* __restrict__ out) {
    int c = blockIdx.x, b = blockIdx.y;
    int tid = threadIdx.x, lane = tid & 31;
    float ls = 0.0f;
    #pragma unroll
    for (int it = 0; it < 4; it++) {
        int hw = it * 256 + tid;
        int n  = (b << 10) + hw;
        int id = g_idx[n];
        float qv = __ldg(cb + (size_t)id * DIM + c);
        size_t off = (size_t)b * DIM * HW + (size_t)c * HW + hw;
        float xv = x[off];
        out[OUT_Q + off] = __fadd_rn(xv, __fsub_rn(qv, xv));
        float d = __fsub_rn(qv, xv);
        ls = fmaf(d, d, ls);
    }
    double ds = (double)ls;
    #pragma unroll
    for (int o = 16; o; o >>= 1) ds += __shfl_down_sync(0xFFFFFFFFu, ds, o);
    if (lane == 0) atomicAdd(&g_loss, ds);
}

// ---------------- dw = segment_sum(flat, idx) ----------------
__global__ void dw_kernel(const float* __restrict__ x) {
    int n = blockIdx.x * blockDim.x + threadIdx.x;
    int d = blockIdx.y;
    int b = n >> 10, hw = n & 1023;
    float v = x[(size_t)b * DIM * HW + (size_t)d * HW + hw];
    atomicAdd(&g_dw[(size_t)g_idx[n] * DIM + d], v);
}

// ---------------- EMA finalize ----------------
__global__ void final_kernel(const float* __restrict__ ema_count,
                             const float* __restrict__ ema_weight,
                             float* __restrict__ out) {
    int k = blockIdx.x;
    int c = threadIdx.x;
    float nc = ema_count[k] * 0.95f + 0.05f * g_counts[k];
    const float denom = (float)(32768.0 + 8192.0 * 1e-5);
    nc = (nc + 1e-5f) / denom * 32768.0f;
    float w = ema_weight[(size_t)k * DIM + c] * 0.95f + 0.05f * g_dw[(size_t)k * DIM + c];
    out[OUT_W  + (size_t)k * DIM + c] = w;
    out[OUT_CB + (size_t)k * DIM + c] = w / nc;
    if (c == 0) out[OUT_CNT + k] = nc;
    if (k == 0 && c == 0) {
        double mean = g_loss / (double)((size_t)NTOK * DIM);
        out[OUT_LOSS] = 0.25f * (float)mean;
    }
}

extern "C" void kernel_launch(void* const* d_in, const int* in_sizes, int n_in,
                              void* d_out, int out_size) {
    const float* x          = (const float*)d_in[0];
    const float* cb         = (const float*)d_in[1];
    const float* ema_count  = (const float*)d_in[2];
    const float* ema_weight = (const float*)d_in[3];
    float* out = (float*)d_out;

    static int smem_set = 0;
    if (!smem_set) {
        cudaFuncSetAttribute(gemm_argmin_tc,
                             cudaFuncAttributeMaxDynamicSharedMemorySize, SMEM_B);
        smem_set = 1;
    }

    init_kernel<<<(K_CODES * DIM + 255) / 256, 256>>>();
    decomp_x<<<NTOK * DIM / 256, 256>>>(x);
    decomp_cbT<<<dim3(K_CODES / 32, DIM / 32), dim3(32, 32)>>>(cb);
    znorm_kernel<<<NTOK / 256, 256>>>(x);
    cbnorm_kernel<<<(K_CODES * 32 + 255) / 256, 256>>>(cb);
    gemm_argmin_tc<<<dim3(K_CODES / 128, NTOK / 128), 256, SMEM_B>>>();
    post_idx<<<NTOK / 256, 256>>>(out);
    quant_loss<<<dim3(DIM, 32), 256>>>(x, cb, out);
    dw_kernel<<<dim3(NTOK / 256, DIM), 256>>>(x);
    final_kernel<<<K_CODES, DIM>>>(ema_count, ema_weight, out);
}

// round 8
// speedup vs baseline: 1.6832x; 1.6832x over previous
#include <cuda_runtime.h>
#include <stdint.h>
#include <math_constants.h>

#define K_CODES 8192
#define DIM     256
#define NTOK    32768
#define HW      1024

// output layout (floats): loss | quantized | indices | new_count | new_weight | new_codebook
#define OUT_LOSS 0
#define OUT_Q    1
#define OUT_IDX  (OUT_Q  + 32*DIM*HW)
#define OUT_CNT  (OUT_IDX + NTOK)
#define OUT_W    (OUT_CNT + K_CODES)
#define OUT_CB   (OUT_W   + K_CODES*DIM)

// ---------------- device scratch ----------------
__device__ __align__(128) float g_xhi[NTOK * DIM];      // x layout: [b][d][hw]
__device__ __align__(128) float g_xlo[NTOK * DIM];
__device__ __align__(128) float g_cbhiT[DIM * K_CODES]; // transposed: [d][code]
__device__ __align__(128) float g_cbloT[DIM * K_CODES];
__device__ float              g_cbnorm[K_CODES];
__device__ float              g_znorm[NTOK];
__device__ unsigned long long g_best[NTOK];
__device__ float              g_counts[K_CODES];
__device__ float              g_dw[K_CODES * DIM];
__device__ double             g_loss;
__device__ int                g_idx[NTOK];

__device__ __forceinline__ uint32_t smem_u32(const void* p) {
    uint32_t a;
    asm("{ .reg .u64 t; cvta.to.shared.u64 t, %1; cvt.u32.u64 %0, t; }" : "=r"(a) : "l"(p));
    return a;
}
__device__ __forceinline__ float to_tf32(float v) {
    uint32_t u;
    asm("cvt.rna.satfinite.tf32.f32 %0, %1;" : "=r"(u) : "f"(v));
    return __uint_as_float(u);
}
#define CP16(dst, src) \
    asm volatile("cp.async.ca.shared.global [%0], [%1], 16;" :: "r"(dst), "l"(src))
#define CP_COMMIT() asm volatile("cp.async.commit_group;" ::: "memory")
#define CP_WAIT1()  asm volatile("cp.async.wait_group 1;" ::: "memory")
#define CP_WAIT0()  asm volatile("cp.async.wait_group 0;" ::: "memory")

#define MMA_TF32(c, a, b) \
    asm volatile("mma.sync.aligned.m16n8k8.row.col.f32.tf32.tf32.f32 " \
        "{%0,%1,%2,%3}, {%4,%5,%6,%7}, {%8,%9}, {%0,%1,%2,%3};" \
        : "+f"((c)[0]), "+f"((c)[1]), "+f"((c)[2]), "+f"((c)[3]) \
        : "r"((a)[0]), "r"((a)[1]), "r"((a)[2]), "r"((a)[3]), "r"((b)[0]), "r"((b)[1]))

// ---------------- init ----------------
__global__ void init_kernel() {
    int i = blockIdx.x * blockDim.x + threadIdx.x;
    if (i < K_CODES * DIM) g_dw[i] = 0.0f;
    if (i < NTOK)          g_best[i] = 0xFFFFFFFFFFFFFFFFull;
    if (i < K_CODES)       g_counts[i] = 0.0f;
    if (i == 0)            g_loss = 0.0;
}

// ---------------- decompose x -> tf32 hi/lo (same layout) ----------------
__global__ void decomp_x(const float* __restrict__ x) {
    int i = blockIdx.x * blockDim.x + threadIdx.x;
    float v  = x[i];
    float hi = to_tf32(v);
    g_xhi[i] = hi;
    g_xlo[i] = to_tf32(v - hi);
}

// ---------------- decompose + transpose codebook -> [d][code] hi/lo ----------------
__global__ void decomp_cbT(const float* __restrict__ cb) {
    __shared__ float tile[32][33];
    int tx = threadIdx.x, ty = threadIdx.y;
    int c0 = blockIdx.x * 32, d0 = blockIdx.y * 32;
    tile[ty][tx] = cb[(size_t)(c0 + ty) * DIM + d0 + tx];
    __syncthreads();
    float v  = tile[tx][ty];                  // code = c0+tx, d = d0+ty
    float hi = to_tf32(v);
    size_t o = (size_t)(d0 + ty) * K_CODES + c0 + tx;
    g_cbhiT[o] = hi;
    g_cbloT[o] = to_tf32(v - hi);
}

// ---------------- token norms (fp64 -> fp32), grid 256 x block 128, 4-way ILP ----
__global__ void znorm_kernel(const float* __restrict__ x) {
    int token = blockIdx.x * blockDim.x + threadIdx.x;
    int b = token >> 10, hw = token & 1023;
    const float* p = x + (size_t)b * DIM * HW + hw;
    double s0 = 0.0, s1 = 0.0, s2 = 0.0, s3 = 0.0;
    #pragma unroll 8
    for (int d = 0; d < DIM; d += 4) {
        double v0 = (double)p[(size_t)(d + 0) * HW];
        double v1 = (double)p[(size_t)(d + 1) * HW];
        double v2 = (double)p[(size_t)(d + 2) * HW];
        double v3 = (double)p[(size_t)(d + 3) * HW];
        s0 = fma(v0, v0, s0);
        s1 = fma(v1, v1, s1);
        s2 = fma(v2, v2, s2);
        s3 = fma(v3, v3, s3);
    }
    g_znorm[token] = (float)((s0 + s1) + (s2 + s3));
}

// ---------------- codebook norms (fp64 -> fp32) ----------------
__global__ void cbnorm_kernel(const float* __restrict__ cb) {
    int gt = blockIdx.x * blockDim.x + threadIdx.x;
    int code = gt >> 5, lane = gt & 31;
    if (code >= K_CODES) return;
    const float* r = cb + (size_t)code * DIM;
    double s = 0.0;
    #pragma unroll
    for (int i = lane; i < DIM; i += 32) {
        double v = (double)__ldg(r + i);
        s = fma(v, v, s);
    }
    #pragma unroll
    for (int o = 16; o; o >>= 1) s += __shfl_down_sync(0xFFFFFFFFu, s, o);
    if (lane == 0) g_cbnorm[code] = (float)s;
}

// ---------------- 3xTF32 mma.sync distance GEMM + argmin ----------------
// grid (64, 256): 128 codes x 128 tokens per CTA; BK=32, 2-stage cp.async.
// smem per stage: Ahi | Alo | Bhi | Blo, each 32 rows x 136 floats (pad 8).
#define ROWP    136
#define ARR_F   (32 * ROWP)          // 4352 floats per array
#define STAGE_F (4 * ARR_F)          // 17408 floats per stage
#define SMEM_B  (2 * STAGE_F * 4)    // 139264 bytes

__global__ void __launch_bounds__(256, 1)
gemm_argmin_tc(void) {
    extern __shared__ float smf[];
    const uint32_t smb = smem_u32(smf);

    const int tid  = threadIdx.x;
    const int lane = tid & 31;
    const int wid  = tid >> 5;
    const int g    = lane >> 2;        // 0..7
    const int q    = lane & 3;         // 0..3

    const int tb  = blockIdx.y;                   // token tile
    const int ct  = blockIdx.x;                   // code tile
    const int b   = (tb * 128) >> 10;
    const int hw0 = (tb * 128) & 1023;
    const int nt0 = ct * 128;

    const int mbase = (wid & 3) * 32;   // warp token offset
    const int nbase = (wid >> 2) * 64;  // warp code offset

    float acc[2][8][4];
    #pragma unroll
    for (int mf = 0; mf < 2; mf++)
        #pragma unroll
        for (int nf = 0; nf < 8; nf++)
            #pragma unroll
            for (int c = 0; c < 4; c++) acc[mf][nf][c] = 0.0f;

    // stage issue: each array tile = 32 rows x 128 floats = 1024 float4;
    // 256 threads x 4 float4 per array. smem row pitch ROWP=136 floats.
    auto issue = [&](int s, int k0) {
        const float* srcA[2] = {
            g_xhi + ((size_t)(b * DIM + k0) << 10) + hw0,
            g_xlo + ((size_t)(b * DIM + k0) << 10) + hw0 };
        const float* srcB[2] = {
            g_cbhiT + ((size_t)k0 << 13) + nt0,
            g_cbloT + ((size_t)k0 << 13) + nt0 };
        #pragma unroll
        for (int arr = 0; arr < 4; arr++) {
            const float* bp = (arr < 2) ? srcA[arr] : srcB[arr - 2];
            const size_t rstride = (arr < 2) ? 1024 : 8192;  // gmem row stride (floats)
            #pragma unroll
            for (int i = 0; i < 4; i++) {
                int idx = i * 256 + tid;         // 0..1023
                int row = idx >> 5;              // 0..31
                int seg = (idx & 31) * 4;        // 0..124
                uint32_t dst = smb + 4u * (s * STAGE_F + arr * ARR_F + row * ROWP + seg);
                CP16(dst, bp + (size_t)row * rstride + seg);
            }
        }
        CP_COMMIT();
    };

    issue(0, 0);

    #pragma unroll 1
    for (int ks = 0; ks < 8; ks++) {
        if (ks < 7) issue((ks + 1) & 1, (ks + 1) * 32);
        if (ks < 7) CP_WAIT1(); else CP_WAIT0();
        __syncthreads();

        const uint32_t* Ah = (const uint32_t*)(smf + (ks & 1) * STAGE_F);
        const uint32_t* Al = Ah + ARR_F;
        const uint32_t* Bh = Al + ARR_F;
        const uint32_t* Bl = Bh + ARR_F;

        #pragma unroll
        for (int kk = 0; kk < 4; kk++) {
            const int r0 = kk * 8 + q;
            const int r1 = r0 + 4;
            uint32_t afh[2][4], afl[2][4], bfh[8][2], bfl[8][2];
            #pragma unroll
            for (int mf = 0; mf < 2; mf++) {
                int m = mbase + mf * 16 + g;
                afh[mf][0] = Ah[r0 * ROWP + m];
                afh[mf][1] = Ah[r0 * ROWP + m + 8];
                afh[mf][2] = Ah[r1 * ROWP + m];
                afh[mf][3] = Ah[r1 * ROWP + m + 8];
                afl[mf][0] = Al[r0 * ROWP + m];
                afl[mf][1] = Al[r0 * ROWP + m + 8];
                afl[mf][2] = Al[r1 * ROWP + m];
                afl[mf][3] = Al[r1 * ROWP + m + 8];
            }
            #pragma unroll
            for (int nf = 0; nf < 8; nf++) {
                int n = nbase + nf * 8 + g;
                bfh[nf][0] = Bh[r0 * ROWP + n];
                bfh[nf][1] = Bh[r1 * ROWP + n];
                bfl[nf][0] = Bl[r0 * ROWP + n];
                bfl[nf][1] = Bl[r1 * ROWP + n];
            }
            // term-outermost: 16 independent accumulators between reuses of any acc.
            // Per-acc term order (hi*hi, hi*lo, lo*hi per k-step) identical to R6.
            #pragma unroll
            for (int mf = 0; mf < 2; mf++)
                #pragma unroll
                for (int nf = 0; nf < 8; nf++)
                    MMA_TF32(acc[mf][nf], afh[mf], bfh[nf]);  // hi*hi
            #pragma unroll
            for (int mf = 0; mf < 2; mf++)
                #pragma unroll
                for (int nf = 0; nf < 8; nf++)
                    MMA_TF32(acc[mf][nf], afh[mf], bfl[nf]);  // hi*lo
            #pragma unroll
            for (int mf = 0; mf < 2; mf++)
                #pragma unroll
                for (int nf = 0; nf < 8; nf++)
                    MMA_TF32(acc[mf][nf], afl[mf], bfh[nf]);  // lo*hi
        }
        __syncthreads();
    }

    // epilogue: d = fl( fl(zn+cn) - 2*dot ), lexicographic (d, idx) min.
    // C frag: c0/c1 at row g (cols 2q, 2q+1), c2/c3 at row g+8.
    #pragma unroll
    for (int mf = 0; mf < 2; mf++) {
        #pragma unroll
        for (int h = 0; h < 2; h++) {
            int m = mbase + mf * 16 + g + h * 8;
            int token = tb * 128 + m;
            float zn = g_znorm[token];
            unsigned long long bestpk = 0xFFFFFFFFFFFFFFFFull;
            #pragma unroll
            for (int nf = 0; nf < 8; nf++) {
                #pragma unroll
                for (int p = 0; p < 2; p++) {
                    int n = nbase + nf * 8 + q * 2 + p;
                    float dot = acc[mf][nf][h * 2 + p];
                    float cn  = __ldg(&g_cbnorm[nt0 + n]);
                    float t1  = __fadd_rn(zn, cn);
                    float d   = __fsub_rn(t1, __fmul_rn(2.0f, dot));
                    unsigned int e = __float_as_uint(d);
                    e = (e & 0x80000000u) ? ~e : (e | 0x80000000u);
                    unsigned long long pk =
                        ((unsigned long long)e << 32) | (unsigned int)(nt0 + n);
                    if (pk < bestpk) bestpk = pk;
                }
            }
            atomicMin(&g_best[token], bestpk);
        }
    }
}

// ---------------- extract indices, bump counts ----------------
__global__ void post_idx(float* __restrict__ out) {
    int n = blockIdx.x * blockDim.x + threadIdx.x;
    if (n >= NTOK) return;
    unsigned long long pk = g_best[n];
    int id = (int)(pk & 0xFFFFFFFFull);
    g_idx[n] = id;
    out[OUT_IDX + n] = (float)id;
    atomicAdd(&g_counts[id], 1.0f);
}

// ---------------- quantized output + commitment loss (coalesced) ----------------
// grid (DIM, 32): block = (c, b); 256 threads x 4 iters over hw.
__global__ void quant_loss(const float* __restrict__ x,
                           const float* __restrict__ cb,
                           float* __restrict__ out) {
    int c = blockIdx.x, b = blockIdx.y;
    int tid = threadIdx.x, lane = tid & 31;
    float ls = 0.0f;
    #pragma unroll
    for (int it = 0; it < 4; it++) {
        int hw = it * 256 + tid;
        int n  = (b << 10) + hw;
        int id = g_idx[n];
        float qv = __ldg(cb + (size_t)id * DIM + c);
        size_t off = (size_t)b * DIM * HW + (size_t)c * HW + hw;
        float xv = x[off];
        out[OUT_Q + off] = __fadd_rn(xv, __fsub_rn(qv, xv));
        float d = __fsub_rn(qv, xv);
        ls = fmaf(d, d, ls);
    }
    double ds = (double)ls;
    #pragma unroll
    for (int o = 16; o; o >>= 1) ds += __shfl_down_sync(0xFFFFFFFFu, ds, o);
    if (lane == 0) atomicAdd(&g_loss, ds);
}

// ---------------- dw = segment_sum(flat, idx) ----------------
__global__ void dw_kernel(const float* __restrict__ x) {
    int n = blockIdx.x * blockDim.x + threadIdx.x;
    int d = blockIdx.y;
    int b = n >> 10, hw = n & 1023;
    float v = x[(size_t)b * DIM * HW + (size_t)d * HW + hw];
    atomicAdd(&g_dw[(size_t)g_idx[n] * DIM + d], v);
}

// ---------------- EMA finalize ----------------
__global__ void final_kernel(const float* __restrict__ ema_count,
                             const float* __restrict__ ema_weight,
                             float* __restrict__ out) {
    int k = blockIdx.x;
    int c = threadIdx.x;
    float nc = ema_count[k] * 0.95f + 0.05f * g_counts[k];
    const float denom = (float)(32768.0 + 8192.0 * 1e-5);
    nc = (nc + 1e-5f) / denom * 32768.0f;
    float w = ema_weight[(size_t)k * DIM + c] * 0.95f + 0.05f * g_dw[(size_t)k * DIM + c];
    out[OUT_W  + (size_t)k * DIM + c] = w;
    out[OUT_CB + (size_t)k * DIM + c] = w / nc;
    if (c == 0) out[OUT_CNT + k] = nc;
    if (k == 0 && c == 0) {
        double mean = g_loss / (double)((size_t)NTOK * DIM);
        out[OUT_LOSS] = 0.25f * (float)mean;
    }
}

extern "C" void kernel_launch(void* const* d_in, const int* in_sizes, int n_in,
                              void* d_out, int out_size) {
    const float* x          = (const float*)d_in[0];
    const float* cb         = (const float*)d_in[1];
    const float* ema_count  = (const float*)d_in[2];
    const float* ema_weight = (const float*)d_in[3];
    float* out = (float*)d_out;

    static int smem_set = 0;
    if (!smem_set) {
        cudaFuncSetAttribute(gemm_argmin_tc,
                             cudaFuncAttributeMaxDynamicSharedMemorySize, SMEM_B);
        smem_set = 1;
    }

    init_kernel<<<(K_CODES * DIM + 255) / 256, 256>>>();
    decomp_x<<<NTOK * DIM / 256, 256>>>(x);
    decomp_cbT<<<dim3(K_CODES / 32, DIM / 32), dim3(32, 32)>>>(cb);
    znorm_kernel<<<NTOK / 128, 128>>>(x);
    cbnorm_kernel<<<(K_CODES * 32 + 255) / 256, 256>>>(cb);
    gemm_argmin_tc<<<dim3(K_CODES / 128, NTOK / 128), 256, SMEM_B>>>();
    post_idx<<<NTOK / 256, 256>>>(out);
    quant_loss<<<dim3(DIM, 32), 256>>>(x, cb, out);
    dw_kernel<<<dim3(NTOK / 256, DIM), 256>>>(x);
    final_kernel<<<K_CODES, DIM>>>(ema_count, ema_weight, out);
}